// round 10
// baseline (speedup 1.0000x reference)
#include <cuda_runtime.h>
#include <cuda_bf16.h>

// Problem constants
#define NB 32            // N
#define MODES 4
#define EYS 192          // EY_SIZE
#define EY_PLANE (EYS*EYS)          // 36864 floats
#define EY_PLANE4 (EY_PLANE/4)      // 9216 float4
#define EYROW4 (EYS/4)              // 48 float4 per Ey row
#define TOTAL 1184       // (N + 2*KNN + 1) * OUT_RES
#define NK (NB*NB)       // 1024

// Fused single kernel. R7 gather (center-out row dispatch) + fixed 6x9 smem
// weight window + PAIRWISE j-loop: each paired iteration keeps 8 float4 Ey
// results + 2 weight vectors live, structurally forcing the high-MLP schedule
// that the LDS-weight variants (R8/R9, regs=44) lost.
// blockDim = (32, 8); grid = (10, 148).
__global__ __launch_bounds__(256) void gather_en_kernel(
    const float* __restrict__ Ey,
    const float* __restrict__ U,
    const float* __restrict__ neff,
    float* __restrict__ out)
{
    // Center-out row remap: heavy interior row-bands dispatch first.
    int byl = blockIdx.y;
    const int by = (byl & 1) ? (74 + (byl >> 1)) : (73 - (byl >> 1));

    const int lane = threadIdx.x;
    const int tid  = threadIdx.y * 32 + lane;
    const int r0   = by * 8;
    const int r    = r0 + threadIdx.y;                 // 0..1183, uniform per warp
    const int c0   = blockIdx.x * 128;
    const int c    = c0 + lane * 4;                    // 16B-aligned column
    const bool active = (c < TOTAL);

    // Unclamped window origins (may be negative): contributing (i,j) satisfy
    // i-iA0 in [0,5], j-jA0 in [0,8].
    const int iA0 = (r0 - 160) >> 5;
    const int jA0 = (c0 - 160) >> 5;

    // Fixed-shape weight window: w_s[(ii*9 + jj)*4 + m], ii<6, jj<9.
    __shared__ float w_s[6 * 9 * MODES];               // 216 floats
    if (tid < 6 * 9 * MODES) {
        const int e  = tid >> 2;                       // 0..53
        const int m  = tid & 3;
        const int ii = e / 9;
        const int jj = e - ii * 9;
        const int i  = iA0 + ii;
        const int j  = jA0 + jj;
        float w = 0.f;
        if ((unsigned)i < NB && (unsigned)j < NB) {
            const int k = (i << 5) + j;
            const float n = neff[k * MODES + m];
            w = U[k * MODES + m] * (n * 1.5f / (n + 1.5f));
        }
        w_s[tid] = w;
    }
    __syncthreads();

    // Per-thread contribution ranges
    int i_lo = (r - 160) >> 5; if (i_lo < 0) i_lo = 0;
    int i_hi = r >> 5;         if (i_hi > NB - 1) i_hi = NB - 1;
    int j_lo = (c - 160) >> 5; if (j_lo < 0) j_lo = 0;
    int j_hi = c >> 5;         if (j_hi > NB - 1) j_hi = NB - 1;
    if (!active) { j_lo = 1; j_hi = 0; }               // tail lanes: no loads

    const float4* __restrict__ Ey4 = reinterpret_cast<const float4*>(Ey);
    const float4* __restrict__ ws4 = reinterpret_cast<const float4*>(w_s);

    float4 acc = make_float4(0.f, 0.f, 0.f, 0.f);

    for (int i = i_lo; i <= i_hi; ++i) {
        const int x = r - (i << 5);                    // 0..191
        const long base_i = (long)(i << 5) * (MODES * EY_PLANE4) + (long)x * EYROW4;
        const int wrow = (i - iA0) * 9 - jA0;          // + j -> smem float4 index

        int j = j_lo;
        // Paired body: 8 independent LDG.128 + 2 LDS.128 per iteration.
        for (; j + 1 <= j_hi; j += 2) {
            const float4* pA = Ey4 + base_i + (long)j * (MODES * EY_PLANE4)
                                   + ((c - (j << 5)) >> 2);
            const float4* pB = pA + (MODES * EY_PLANE4 - 8);   // j+1: +plane, y4-8

            const float4 wA = ws4[wrow + j];
            const float4 wB = ws4[wrow + j + 1];

            const float4 a0 = __ldg(pA);
            const float4 a1 = __ldg(pA + EY_PLANE4);
            const float4 a2 = __ldg(pA + 2 * EY_PLANE4);
            const float4 a3 = __ldg(pA + 3 * EY_PLANE4);
            const float4 b0 = __ldg(pB);
            const float4 b1 = __ldg(pB + EY_PLANE4);
            const float4 b2 = __ldg(pB + 2 * EY_PLANE4);
            const float4 b3 = __ldg(pB + 3 * EY_PLANE4);

            acc.x += wA.x * a0.x + wA.y * a1.x + wA.z * a2.x + wA.w * a3.x;
            acc.y += wA.x * a0.y + wA.y * a1.y + wA.z * a2.y + wA.w * a3.y;
            acc.z += wA.x * a0.z + wA.y * a1.z + wA.z * a2.z + wA.w * a3.z;
            acc.w += wA.x * a0.w + wA.y * a1.w + wA.z * a2.w + wA.w * a3.w;

            acc.x += wB.x * b0.x + wB.y * b1.x + wB.z * b2.x + wB.w * b3.x;
            acc.y += wB.x * b0.y + wB.y * b1.y + wB.z * b2.y + wB.w * b3.y;
            acc.z += wB.x * b0.z + wB.y * b1.z + wB.z * b2.z + wB.w * b3.z;
            acc.w += wB.x * b0.w + wB.y * b1.w + wB.z * b2.w + wB.w * b3.w;
        }
        // Epilogue: odd remainder
        if (j <= j_hi) {
            const float4* p = Ey4 + base_i + (long)j * (MODES * EY_PLANE4)
                                  + ((c - (j << 5)) >> 2);
            const float4 wv = ws4[wrow + j];

            const float4 e0 = __ldg(p);
            const float4 e1 = __ldg(p + EY_PLANE4);
            const float4 e2 = __ldg(p + 2 * EY_PLANE4);
            const float4 e3 = __ldg(p + 3 * EY_PLANE4);

            acc.x += wv.x * e0.x + wv.y * e1.x + wv.z * e2.x + wv.w * e3.x;
            acc.y += wv.x * e0.y + wv.y * e1.y + wv.z * e2.y + wv.w * e3.y;
            acc.z += wv.x * e0.z + wv.y * e1.z + wv.z * e2.z + wv.w * e3.z;
            acc.w += wv.x * e0.w + wv.y * e1.w + wv.z * e2.w + wv.w * e3.w;
        }
    }

    if (active) {
        *reinterpret_cast<float4*>(out + (long)r * TOTAL + c) = acc;
    }
}

extern "C" void kernel_launch(void* const* d_in, const int* in_sizes, int n_in,
                              void* d_out, int out_size) {
    // Inputs (metadata order): hs (unused), U, neff, Ey
    const float* U    = (const float*)d_in[1];
    const float* neff = (const float*)d_in[2];
    const float* Ey   = (const float*)d_in[3];
    float* out = (float*)d_out;

    dim3 block(32, 8);
    dim3 grid((TOTAL + 127) / 128, TOTAL / 8);   // (10, 148)
    gather_en_kernel<<<grid, block>>>(Ey, U, neff, out);
}

// round 11
// speedup vs baseline: 1.0003x; 1.0003x over previous
#include <cuda_runtime.h>
#include <cuda_bf16.h>

// Problem constants
#define NB 32            // N
#define MODES 4
#define EYS 192          // EY_SIZE
#define EY_PLANE (EYS*EYS)          // 36864 floats
#define EY_PLANE4 (EY_PLANE/4)      // 9216 float4
#define EYROW4 (EYS/4)              // 48 float4 per Ey row
#define TOTAL 1184       // (N + 2*KNN + 1) * OUT_RES
#define NK (NB*NB)       // 1024

// Scratch: precomputed weights w[k][m] = U * neff*N0/(neff+N0), laid out [k*4+m]
__device__ float g_w[NK * MODES];

__global__ void compute_weights_kernel(const float* __restrict__ U,
                                       const float* __restrict__ neff) {
    int idx = blockIdx.x * blockDim.x + threadIdx.x;
    if (idx < NK * MODES) {
        float nf = neff[idx];
        float eta = nf * 1.5f / (nf + 1.5f);
        g_w[idx] = eta * U[idx];
    }
}

// R7 inner loop VERBATIM (proven optimum: single-j, 4 front-batched LDG.128,
// LDG weight). One change: 128-thread CTAs (32x4) -> 2960 CTAs, ~5 waves,
// halved drain-tail quantum. Center-out row dispatch kept (296 row-bands).
// blockDim = (32, 4); grid = (10, 296).
__global__ __launch_bounds__(128) void gather_en_kernel(
    const float* __restrict__ Ey,
    float* __restrict__ out)
{
    // Center-out row remap over 296 bands: heavy interior bands dispatch first.
    int byl = blockIdx.y;
    const int by = (byl & 1) ? (148 + (byl >> 1)) : (147 - (byl >> 1));

    const int lane = threadIdx.x;
    const int r    = by * 4 + threadIdx.y;             // 0..1183, uniform per warp
    const int c    = blockIdx.x * 128 + lane * 4;      // 16B-aligned column
    const bool active = (c < TOTAL);

    // i-range uniform per warp
    int i_lo = (r - 160) >> 5; if (i_lo < 0) i_lo = 0;
    int i_hi = r >> 5;         if (i_hi > NB - 1) i_hi = NB - 1;

    // j-range per lane
    int j_lo = (c - 160) >> 5; if (j_lo < 0) j_lo = 0;
    int j_hi = c >> 5;         if (j_hi > NB - 1) j_hi = NB - 1;
    if (!active) { j_lo = 1; j_hi = 0; }               // tail lanes: no loads

    const float4* __restrict__ w4  = reinterpret_cast<const float4*>(g_w);
    const float4* __restrict__ Ey4 = reinterpret_cast<const float4*>(Ey);

    float4 acc = make_float4(0.f, 0.f, 0.f, 0.f);

    for (int i = i_lo; i <= i_hi; ++i) {
        const int x = r - (i << 5);                    // 0..191
        const long base_i = (long)(i << 5) * (MODES * EY_PLANE4) + (long)x * EYROW4;
        for (int j = j_lo; j <= j_hi; ++j) {
            const int k  = (i << 5) + j;
            const int y4 = (c - (j << 5)) >> 2;        // 0..47 float4 within row
            const float4* p = Ey4 + base_i + (long)j * (MODES * EY_PLANE4) + y4;
            const float4 wv = __ldg(&w4[k]);           // uniform per warp, L1-hot

            const float4 e0 = __ldg(p);
            const float4 e1 = __ldg(p + EY_PLANE4);
            const float4 e2 = __ldg(p + 2 * EY_PLANE4);
            const float4 e3 = __ldg(p + 3 * EY_PLANE4);

            acc.x += wv.x * e0.x + wv.y * e1.x + wv.z * e2.x + wv.w * e3.x;
            acc.y += wv.x * e0.y + wv.y * e1.y + wv.z * e2.y + wv.w * e3.y;
            acc.z += wv.x * e0.z + wv.y * e1.z + wv.z * e2.z + wv.w * e3.z;
            acc.w += wv.x * e0.w + wv.y * e1.w + wv.z * e2.w + wv.w * e3.w;
        }
    }

    if (active) {
        *reinterpret_cast<float4*>(out + (long)r * TOTAL + c) = acc;
    }
}

extern "C" void kernel_launch(void* const* d_in, const int* in_sizes, int n_in,
                              void* d_out, int out_size) {
    // Inputs (metadata order): hs (unused), U, neff, Ey
    const float* U    = (const float*)d_in[1];
    const float* neff = (const float*)d_in[2];
    const float* Ey   = (const float*)d_in[3];
    float* out = (float*)d_out;

    compute_weights_kernel<<<(NK * MODES + 255) / 256, 256>>>(U, neff);

    dim3 block(32, 4);
    dim3 grid((TOTAL + 127) / 128, TOTAL / 4);   // (10, 296)
    gather_en_kernel<<<grid, block>>>(Ey, out);
}

// round 12
// speedup vs baseline: 1.0121x; 1.0118x over previous
#include <cuda_runtime.h>
#include <cuda_bf16.h>

// Problem constants
#define NB 32            // N
#define MODES 4
#define EYS 192          // EY_SIZE
#define EY_PLANE (EYS*EYS)          // 36864 floats
#define EY_PLANE4 (EY_PLANE/4)      // 9216 float4
#define EYROW4 (EYS/4)              // 48 float4 per Ey row
#define TOTAL 1184       // (N + 2*KNN + 1) * OUT_RES
#define NK (NB*NB)       // 1024

#define NTILES 1480      // 148 row-bands x 10 col-bands
#define NPERSIST 592     // 148 SMs x 4 CTAs/SM

// Scratch: precomputed weights w[k][m] = U * neff*N0/(neff+N0), laid out [k*4+m]
__device__ float g_w[NK * MODES];
__device__ unsigned int g_ticket;

__global__ void compute_weights_kernel(const float* __restrict__ U,
                                       const float* __restrict__ neff) {
    int idx = blockIdx.x * blockDim.x + threadIdx.x;
    if (idx == 0) g_ticket = 0u;                       // reset work queue
    if (idx < NK * MODES) {
        float nf = neff[idx];
        float eta = nf * 1.5f / (nf + 1.5f);
        g_w[idx] = eta * U[idx];
    }
}

// Persistent-CTA version of the R7 gather (body verbatim). 592 resident CTAs
// claim tiles from an atomic ticket; tiles ordered heavy->light (center-out
// rows AND columns) so the queue drains to cheap edge tiles at the end.
__global__ __launch_bounds__(256) void gather_en_kernel(
    const float* __restrict__ Ey,
    float* __restrict__ out)
{
    const int lane = threadIdx.x;
    const int wy   = threadIdx.y;
    const int tid  = wy * 32 + lane;

    const float4* __restrict__ w4  = reinterpret_cast<const float4*>(g_w);
    const float4* __restrict__ Ey4 = reinterpret_cast<const float4*>(Ey);

    __shared__ unsigned int s_tile;

    for (;;) {
        __syncthreads();                               // protect s_tile reuse
        if (tid == 0) s_tile = atomicAdd(&g_ticket, 1u);
        __syncthreads();
        const unsigned int t = s_tile;
        if (t >= NTILES) break;

        // Heavy-first tile decode: center-out in rows (148 bands) and cols (10).
        const int byl = t / 10;
        const int bxl = t - byl * 10;
        const int by  = (byl & 1) ? (74 + (byl >> 1)) : (73 - (byl >> 1));
        const int bx  = (bxl & 1) ? (4 - (bxl >> 1))  : (5 + (bxl >> 1));

        const int r = by * 8 + wy;                     // 0..1183, uniform per warp
        const int c = bx * 128 + lane * 4;             // 16B-aligned column
        const bool active = (c < TOTAL);

        // i-range uniform per warp
        int i_lo = (r - 160) >> 5; if (i_lo < 0) i_lo = 0;
        int i_hi = r >> 5;         if (i_hi > NB - 1) i_hi = NB - 1;

        // j-range per lane
        int j_lo = (c - 160) >> 5; if (j_lo < 0) j_lo = 0;
        int j_hi = c >> 5;         if (j_hi > NB - 1) j_hi = NB - 1;
        if (!active) { j_lo = 1; j_hi = 0; }           // tail lanes: no loads

        float4 acc = make_float4(0.f, 0.f, 0.f, 0.f);

        for (int i = i_lo; i <= i_hi; ++i) {
            const int x = r - (i << 5);                // 0..191
            const long base_i = (long)(i << 5) * (MODES * EY_PLANE4)
                              + (long)x * EYROW4;
            for (int j = j_lo; j <= j_hi; ++j) {
                const int k  = (i << 5) + j;
                const int y4 = (c - (j << 5)) >> 2;    // 0..47 float4 within row
                const float4* p = Ey4 + base_i + (long)j * (MODES * EY_PLANE4) + y4;
                const float4 wv = __ldg(&w4[k]);       // uniform per warp, L1-hot

                const float4 e0 = __ldg(p);
                const float4 e1 = __ldg(p + EY_PLANE4);
                const float4 e2 = __ldg(p + 2 * EY_PLANE4);
                const float4 e3 = __ldg(p + 3 * EY_PLANE4);

                acc.x += wv.x * e0.x + wv.y * e1.x + wv.z * e2.x + wv.w * e3.x;
                acc.y += wv.x * e0.y + wv.y * e1.y + wv.z * e2.y + wv.w * e3.y;
                acc.z += wv.x * e0.z + wv.y * e1.z + wv.z * e2.z + wv.w * e3.z;
                acc.w += wv.x * e0.w + wv.y * e1.w + wv.z * e2.w + wv.w * e3.w;
            }
        }

        if (active) {
            *reinterpret_cast<float4*>(out + (long)r * TOTAL + c) = acc;
        }
    }
}

extern "C" void kernel_launch(void* const* d_in, const int* in_sizes, int n_in,
                              void* d_out, int out_size) {
    // Inputs (metadata order): hs (unused), U, neff, Ey
    const float* U    = (const float*)d_in[1];
    const float* neff = (const float*)d_in[2];
    const float* Ey   = (const float*)d_in[3];
    float* out = (float*)d_out;

    compute_weights_kernel<<<(NK * MODES + 255) / 256, 256>>>(U, neff);

    dim3 block(32, 8);
    gather_en_kernel<<<NPERSIST, block>>>(Ey, out);
}

// round 13
// speedup vs baseline: 1.0671x; 1.0543x over previous
#include <cuda_runtime.h>
#include <cuda_bf16.h>

// Problem constants
#define NB 32            // N
#define MODES 4
#define EYS 192          // EY_SIZE
#define EY_PLANE (EYS*EYS)          // 36864 floats
#define EY_PLANE4 (EY_PLANE/4)      // 9216 float4
#define EYROW4 (EYS/4)              // 48 float4 per Ey row
#define TOTAL 1184       // (N + 2*KNN + 1) * OUT_RES
#define NK (NB*NB)       // 1024

// Scratch: precomputed weights w[k][m] = U * neff*N0/(neff+N0), laid out [k*4+m]
__device__ float g_w[NK * MODES];

__global__ void compute_weights_kernel(const float* __restrict__ U,
                                       const float* __restrict__ neff) {
    int idx = blockIdx.x * blockDim.x + threadIdx.x;
    if (idx < NK * MODES) {
        float nf = neff[idx];
        float eta = nf * 1.5f / (nf + 1.5f);
        g_w[idx] = eta * U[idx];
    }
}

// R7 gather VERBATIM (center-out rows, natural columns, single-j inner loop
// with 4 front-batched LDG.128 + LDG weight) + PDL: launched with
// programmatic stream serialization so the prologue overlaps the weights
// kernel; cudaGridDependencySynchronize() gates the first g_w read.
// blockDim = (32, 8); grid = (10, 148).
__global__ __launch_bounds__(256) void gather_en_kernel(
    const float* __restrict__ Ey,
    float* __restrict__ out)
{
    // Center-out row remap: heavy interior row-bands dispatch first.
    int byl = blockIdx.y;
    const int by = (byl & 1) ? (74 + (byl >> 1)) : (73 - (byl >> 1));

    const int lane = threadIdx.x;
    const int r    = by * 8 + threadIdx.y;             // 0..1183, uniform per warp
    const int c    = blockIdx.x * 128 + lane * 4;      // 16B-aligned column
    const bool active = (c < TOTAL);

    // i-range uniform per warp
    int i_lo = (r - 160) >> 5; if (i_lo < 0) i_lo = 0;
    int i_hi = r >> 5;         if (i_hi > NB - 1) i_hi = NB - 1;

    // j-range per lane
    int j_lo = (c - 160) >> 5; if (j_lo < 0) j_lo = 0;
    int j_hi = c >> 5;         if (j_hi > NB - 1) j_hi = NB - 1;
    if (!active) { j_lo = 1; j_hi = 0; }               // tail lanes: no loads

    const float4* __restrict__ w4  = reinterpret_cast<const float4*>(g_w);
    const float4* __restrict__ Ey4 = reinterpret_cast<const float4*>(Ey);

    // Wait for the weights kernel (PDL): all prologue above ran concurrently.
    cudaGridDependencySynchronize();

    float4 acc = make_float4(0.f, 0.f, 0.f, 0.f);

    for (int i = i_lo; i <= i_hi; ++i) {
        const int x = r - (i << 5);                    // 0..191
        const long base_i = (long)(i << 5) * (MODES * EY_PLANE4) + (long)x * EYROW4;
        for (int j = j_lo; j <= j_hi; ++j) {
            const int k  = (i << 5) + j;
            const int y4 = (c - (j << 5)) >> 2;        // 0..47 float4 within row
            const float4* p = Ey4 + base_i + (long)j * (MODES * EY_PLANE4) + y4;
            const float4 wv = __ldg(&w4[k]);           // uniform per warp, L1-hot

            const float4 e0 = __ldg(p);
            const float4 e1 = __ldg(p + EY_PLANE4);
            const float4 e2 = __ldg(p + 2 * EY_PLANE4);
            const float4 e3 = __ldg(p + 3 * EY_PLANE4);

            acc.x += wv.x * e0.x + wv.y * e1.x + wv.z * e2.x + wv.w * e3.x;
            acc.y += wv.x * e0.y + wv.y * e1.y + wv.z * e2.y + wv.w * e3.y;
            acc.z += wv.x * e0.z + wv.y * e1.z + wv.z * e2.z + wv.w * e3.z;
            acc.w += wv.x * e0.w + wv.y * e1.w + wv.z * e2.w + wv.w * e3.w;
        }
    }

    if (active) {
        *reinterpret_cast<float4*>(out + (long)r * TOTAL + c) = acc;
    }
}

extern "C" void kernel_launch(void* const* d_in, const int* in_sizes, int n_in,
                              void* d_out, int out_size) {
    // Inputs (metadata order): hs (unused), U, neff, Ey
    const float* U    = (const float*)d_in[1];
    const float* neff = (const float*)d_in[2];
    const float* Ey   = (const float*)d_in[3];
    float* out = (float*)d_out;

    compute_weights_kernel<<<(NK * MODES + 255) / 256, 256>>>(U, neff);

    // Launch gather with programmatic dependent launch: its prologue overlaps
    // the weights kernel; cudaGridDependencySynchronize() inside gates g_w.
    dim3 block(32, 8);
    dim3 grid((TOTAL + 127) / 128, TOTAL / 8);   // (10, 148)

    cudaLaunchConfig_t cfg = {};
    cfg.gridDim  = grid;
    cfg.blockDim = block;
    cfg.dynamicSmemBytes = 0;
    cfg.stream = 0;
    cudaLaunchAttribute attrs[1];
    attrs[0].id = cudaLaunchAttributeProgrammaticStreamSerialization;
    attrs[0].val.programmaticStreamSerializationAllowed = 1;
    cfg.attrs = attrs;
    cfg.numAttrs = 1;
    cudaLaunchKernelEx(&cfg, gather_en_kernel, Ey, out);
}